// round 12
// baseline (speedup 1.0000x reference)
#include <cuda_runtime.h>
#include <math.h>
#include <stdint.h>

#define NTAG 36
#define SEQ  512
#define HID  512
#define EMB  512
#define G4   2048   // 4*HID
#define NCTA 64     // fewer barrier participants -> smaller arrival wave + tail skew

// ---------------- device scratch (no allocations allowed) ----------------
__device__ __align__(16) float g_embeds[SEQ * EMB];        // 1 MB
__device__ __align__(16) float g_P[SEQ * G4];              // 4 MB: Wih@x + bih + bhh
__device__ __align__(16) float g_h[2][HID];
__device__ __align__(16) float g_c[HID];
__device__ int g_tag_list[NTAG * SEQ];
__device__ int g_tag_cnt[NTAG];
__device__ __align__(128) unsigned g_ctr;   // cumulative arrival counter

__device__ __forceinline__ float sigmoidf_(float x) {
    return 1.0f / (1.0f + __expf(-x));
}
__device__ __forceinline__ void cp16(uint32_t smem_addr, const void* gptr) {
    asm volatile("cp.async.cg.shared.global [%0], [%1], 16;\n"
                 :: "r"(smem_addr), "l"(gptr));
}
__device__ __forceinline__ unsigned ld_acq_u32(const unsigned* p) {
    unsigned v;
    asm volatile("ld.global.acquire.gpu.b32 %0, [%1];" : "=r"(v) : "l"(p));
    return v;
}
__device__ __forceinline__ void red_rel_add(unsigned* p, unsigned v) {
    asm volatile("red.global.release.gpu.add.u32 [%0], %1;" :: "l"(p), "r"(v) : "memory");
}

// ---------------- init ----------------
__global__ void k_init(const float* __restrict__ h0, const float* __restrict__ c0,
                       const int* __restrict__ tags) {
    int j = threadIdx.x;            // 512 threads
    g_h[0][j] = h0[j];
    g_c[j]    = c0[j];
    if (j < NTAG) g_tag_cnt[j] = 0;
    if (j == 0)   g_ctr = 0;
    __syncthreads();
    int tag = tags[j];
    int pos = atomicAdd(&g_tag_cnt[tag], 1);
    g_tag_list[tag * SEQ + pos] = j;
}

// ---------------- embedding gather ----------------
__global__ void k_embed(const int* __restrict__ x, const float* __restrict__ emb) {
    int t = blockIdx.x;             // grid 512, block 128
    int row = x[t];
    const float4* src = (const float4*)emb + (size_t)row * (EMB / 4);
    float4* dst = (float4*)g_embeds + (size_t)t * (EMB / 4);
    dst[threadIdx.x] = src[threadIdx.x];
}

// ---------------- precompute P[t] = Wih[tag_t] @ x_t + bih + bhh (148us config) ----
__global__ void k_precompute(const float* __restrict__ Wih,
                             const float* __restrict__ bih,
                             const float* __restrict__ bhh) {
    __shared__ float4 Xs[16 * 128];
    __shared__ int ts[16];
    int g   = blockIdx.x;
    int cnt = g_tag_cnt[g];
    int c0  = blockIdx.z * 16;
    if (c0 >= cnt) return;
    int m   = min(16, cnt - c0);
    int tid = threadIdx.x;

    if (tid < 16) ts[tid] = (tid < m) ? g_tag_list[g * SEQ + c0 + tid] : 0;
    __syncthreads();

    #pragma unroll
    for (int it = 0; it < 16; ++it) {
        int i = it * 128 + tid;
        int n = i >> 7, kk = i & 127;
        Xs[i] = (n < m) ? ((const float4*)g_embeds)[(size_t)ts[n] * 128 + kk]
                        : make_float4(0.f, 0.f, 0.f, 0.f);
    }
    __syncthreads();

    int r = blockIdx.y * 128 + tid;
    const float4* wrow = (const float4*)(Wih + ((size_t)g * G4 + r) * EMB);

    float acc[16];
    #pragma unroll
    for (int n = 0; n < 16; ++n) acc[n] = 0.f;

    #pragma unroll 2
    for (int kk = 0; kk < 128; ++kk) {
        float4 w = __ldg(wrow + kk);
        #pragma unroll
        for (int n = 0; n < 16; ++n) {
            float4 xv = Xs[n * 128 + kk];
            acc[n] += w.x * xv.x + w.y * xv.y + w.z * xv.z + w.w * xv.w;
        }
    }

    float bias = bih[g * G4 + r] + bhh[g * G4 + r];
    for (int n = 0; n < m; ++n)
        g_P[(size_t)ts[n] * G4 + r] = acc[n] + bias;
}

// ---------------- persistent recurrent kernel ----------------
// 64 CTAs x 544 threads (17 warps). CTA b owns j in [8b, 8b+8).
// warp 0: sync/h/gates (all 32 lanes: one gate nonlinearity each).
// warps 1-16 (idx=w-1): jl=idx&7, gate pair p=(idx>>3)*2,
//   rows {p*512 + 8b+jl, (p+1)*512 + 8b+jl}. cp.async double-buffered ring.
__global__ void __launch_bounds__(544, 1) k_seq(const float* __restrict__ Whh,
                                                const int* __restrict__ tags_g) {
    extern __shared__ char dsm[];
    float*  wsb   = (float*)dsm;                          // [2][16 warps][1024] 128 KB
    float4* hs4   = (float4*)(dsm + 131072);              // h stage, 512 floats
    int*    stags = (int*)  (dsm + 131072 + 2048);        // 512 ints
    float*  sred  = (float*)(dsm + 131072 + 4096);        // 32 floats

    int tid  = threadIdx.x;
    int lane = tid & 31;
    int w    = tid >> 5;                 // 0..16
    int b    = blockIdx.x;
    int idx  = w - 1;                    // compute-warp index 0..15 (w>=1)
    int j    = b * 8 + (idx & 7);
    int r0   = ((idx >> 3) * 2) * HID + j;   // first of the warp's two rows

    for (int i = tid; i < SEQ; i += 544) stags[i] = tags_g[i];
    __syncthreads();

    // warp 0 lanes 0-7 carry c for j = 8b+lane
    float c = (w == 0 && lane < 8) ? g_c[b * 8 + lane] : 0.f;

    uint32_t wbase = 0;
    const size_t ROWSTRIDE = (size_t)HID;
    if (w > 0) {
        wbase = (uint32_t)__cvta_generic_to_shared(wsb + idx * 1024);
        #pragma unroll
        for (int s = 0; s < 2; ++s) {
            const float* s0 = Whh + ((size_t)stags[s] * G4 + r0) * ROWSTRIDE;
            const float* s1 = s0 + 512 * ROWSTRIDE;
            uint32_t d = wbase + s * 65536;     // slot stride = 16 warps * 4KB
            #pragma unroll
            for (int k = 0; k < 4; ++k) {
                cp16(d +        (lane + 32 * k) * 16, s0 + (lane + 32 * k) * 4);
                cp16(d + 2048 + (lane + 32 * k) * 16, s1 + (lane + 32 * k) * 4);
            }
            asm volatile("cp.async.commit_group;\n" ::: "memory");
        }
    }

    // warp 0: lane L handles gate (L>>3) of j-local (L&7)
    int jl = lane & 7;
    int gg = lane >> 3;
    int sidx = (gg < 2) ? (2 * jl + gg) : (16 + 2 * jl + (gg - 2));
    float pv = 0.f;

    for (int t = 0; t < SEQ; ++t) {
        int slot = t & 1;

        if (w == 0) {
            // P prefetch: one element per lane (gate gg, column j)
            pv = __ldg(g_P + (size_t)t * G4 + gg * 512 + b * 8 + jl);
            // poll with backoff, then fetch h -> smem
            unsigned target = (unsigned)NCTA * (unsigned)t;
            if (ld_acq_u32(&g_ctr) < target) {
                do { __nanosleep(200); } while (ld_acq_u32(&g_ctr) < target);
            }
            const float4* hg = (const float4*)g_h[t & 1];
            hs4[lane]      = __ldcg(hg + lane);
            hs4[lane + 32] = __ldcg(hg + lane + 32);
            hs4[lane + 64] = __ldcg(hg + lane + 64);
            hs4[lane + 96] = __ldcg(hg + lane + 96);
            __syncthreads();   // bar1: h staged
            __syncthreads();   // bar2: sred ready

            // branch-free nonlinearity: gate 2 -> tanh, else sigmoid
            float val = sred[sidx] + pv;
            float arg = (gg == 2) ? (2.0f * val) : val;
            float r1  = 1.0f / (1.0f + __expf(-arg));
            float nl  = (gg == 2) ? (2.0f * r1 - 1.0f) : r1;

            float iv = nl;   // valid in lanes 0-7
            float fv = __shfl_sync(0xffffffffu, nl, lane + 8);
            float gv = __shfl_sync(0xffffffffu, nl, lane + 16);
            float ov = __shfl_sync(0xffffffffu, nl, lane + 24);

            float hv = 0.f;
            if (lane < 8) {
                c = fv * c + iv * gv;
                float e2 = __expf(-2.0f * c);
                hv = ov * (2.0f / (1.0f + e2) - 1.0f);
            }
            // pack 8 h values into lane 0, two STG.128, one release
            float v1 = __shfl_sync(0xffffffffu, hv, 1);
            float v2 = __shfl_sync(0xffffffffu, hv, 2);
            float v3 = __shfl_sync(0xffffffffu, hv, 3);
            float v4 = __shfl_sync(0xffffffffu, hv, 4);
            float v5 = __shfl_sync(0xffffffffu, hv, 5);
            float v6 = __shfl_sync(0xffffffffu, hv, 6);
            float v7 = __shfl_sync(0xffffffffu, hv, 7);
            if (lane == 0) {
                float* hb = &g_h[(t + 1) & 1][b * 8];
                *(float4*)(hb)     = make_float4(hv, v1, v2, v3);
                *(float4*)(hb + 4) = make_float4(v4, v5, v6, v7);
                red_rel_add(&g_ctr, 1u);    // release orders both stores
            }
        } else {
            // compute warps: weight LDS + refill overlap warp 0's poll
            asm volatile("cp.async.wait_group 1;\n" ::: "memory");
            const float4* wr = (const float4*)(wsb + slot * 16384 + idx * 1024);
            float4 b0 = wr[lane],            b1 = wr[lane + 32];
            float4 b2 = wr[lane + 64],       b3 = wr[lane + 96];
            float4 e0 = wr[128 + lane],      e1 = wr[128 + lane + 32];
            float4 e2 = wr[128 + lane + 64], e3 = wr[128 + lane + 96];

            if (t + 2 < SEQ) {
                const float* s0 = Whh + ((size_t)stags[t + 2] * G4 + r0) * ROWSTRIDE;
                const float* s1 = s0 + 512 * ROWSTRIDE;
                uint32_t d = wbase + slot * 65536;
                #pragma unroll
                for (int k = 0; k < 4; ++k) {
                    cp16(d +        (lane + 32 * k) * 16, s0 + (lane + 32 * k) * 4);
                    cp16(d + 2048 + (lane + 32 * k) * 16, s1 + (lane + 32 * k) * 4);
                }
            }
            asm volatile("cp.async.commit_group;\n" ::: "memory");

            __syncthreads();   // bar1: wait for h in smem

            float4 h0 = hs4[lane];
            float4 h1 = hs4[lane + 32];
            float4 h2 = hs4[lane + 64];
            float4 h3 = hs4[lane + 96];
            float acc0 = b0.x*h0.x + b0.y*h0.y + b0.z*h0.z + b0.w*h0.w
                       + b1.x*h1.x + b1.y*h1.y + b1.z*h1.z + b1.w*h1.w
                       + b2.x*h2.x + b2.y*h2.y + b2.z*h2.z + b2.w*h2.w
                       + b3.x*h3.x + b3.y*h3.y + b3.z*h3.z + b3.w*h3.w;
            float acc1 = e0.x*h0.x + e0.y*h0.y + e0.z*h0.z + e0.w*h0.w
                       + e1.x*h1.x + e1.y*h1.y + e1.z*h1.z + e1.w*h1.w
                       + e2.x*h2.x + e2.y*h2.y + e2.z*h2.z + e2.w*h2.w
                       + e3.x*h3.x + e3.y*h3.y + e3.z*h3.z + e3.w*h3.w;
            #pragma unroll
            for (int off = 16; off; off >>= 1) {
                acc0 += __shfl_down_sync(0xffffffffu, acc0, off);
                acc1 += __shfl_down_sync(0xffffffffu, acc1, off);
            }
            // sred layout: gates i,f at [2jl],[2jl+1] (idx<8); g,o at [16+2jl],[17+2jl]
            if (lane == 0) {
                int base = (idx < 8) ? (2 * (idx & 7)) : (16 + 2 * (idx & 7));
                sred[base]     = acc0;
                sred[base + 1] = acc1;
            }
            __syncthreads();   // bar2: sred published
        }
    }

    if (w == 0 && lane < 8) g_c[b * 8 + lane] = c;
}

// ---------------- final fc + sigmoid + pack outputs ----------------
__global__ void k_final(const float* __restrict__ Wfc, const float* __restrict__ bfc,
                        float* __restrict__ out, int out_size) {
    __shared__ float red[16];
    int tid = threadIdx.x;            // 512 threads
    float hv = g_h[0][tid];           // after step 511, h lives in buffer 0
    float v = hv * Wfc[tid];
    #pragma unroll
    for (int off = 16; off; off >>= 1) v += __shfl_down_sync(0xffffffffu, v, off);
    if ((tid & 31) == 0) red[tid >> 5] = v;
    __syncthreads();
    if (tid < 16) {
        float s = red[tid];
        #pragma unroll
        for (int off = 8; off; off >>= 1) s += __shfl_down_sync(0x0000ffffu, s, off);
        if (tid == 0 && out_size > 0)
            out[0] = sigmoidf_(s + bfc[0]);
    }
    if (1 + tid < out_size)   out[1 + tid]   = hv;
    if (513 + tid < out_size) out[513 + tid] = g_c[tid];
}

// ---------------- launcher ----------------
extern "C" void kernel_launch(void* const* d_in, const int* in_sizes, int n_in,
                              void* d_out, int out_size) {
    const int*   x    = (const int*)d_in[0];
    const int*   tags = (const int*)d_in[1];
    const float* h0   = (const float*)d_in[2];
    const float* c0   = (const float*)d_in[3];
    const float* emb  = (const float*)d_in[4];
    const float* Wih  = (const float*)d_in[5];
    const float* Whh  = (const float*)d_in[6];
    const float* bih  = (const float*)d_in[7];
    const float* bhh  = (const float*)d_in[8];
    const float* Wfc  = (const float*)d_in[9];
    const float* bfc  = (const float*)d_in[10];
    (void)in_sizes; (void)n_in;

    const int SMEM_SEQ = 131072 + 2048 + 2048 + 256;   // ~132.5 KB dynamic
    cudaFuncSetAttribute(k_seq, cudaFuncAttributeMaxDynamicSharedMemorySize, SMEM_SEQ);

    k_init<<<1, 512>>>(h0, c0, tags);
    k_embed<<<512, 128>>>(x, emb);
    k_precompute<<<dim3(NTAG, 16, 32), 128>>>(Wih, bih, bhh);
    k_seq<<<NCTA, 544, SMEM_SEQ>>>(Whh, tags);
    k_final<<<1, 512>>>(Wfc, bfc, (float*)d_out, out_size);
}

// round 13
// speedup vs baseline: 1.0770x; 1.0770x over previous
#include <cuda_runtime.h>
#include <math.h>
#include <stdint.h>

#define NTAG 36
#define SEQ  512
#define HID  512
#define EMB  512
#define G4   2048   // 4*HID
#define NCTA 128

// ---------------- device scratch (no allocations allowed) ----------------
__device__ __align__(16) float g_embeds[SEQ * EMB];        // 1 MB
__device__ __align__(16) float g_P[SEQ * G4];              // 4 MB: Wih@x + bih + bhh
__device__ __align__(16) float g_h[2][HID];
__device__ __align__(16) float g_c[HID];
__device__ int g_tag_list[NTAG * SEQ];
__device__ int g_tag_cnt[NTAG];
__device__ __align__(128) unsigned g_ctr;   // cumulative arrival counter

__device__ __forceinline__ float sigmoidf_(float x) {
    return 1.0f / (1.0f + __expf(-x));
}
__device__ __forceinline__ void cp16(uint32_t smem_addr, const void* gptr) {
    asm volatile("cp.async.cg.shared.global [%0], [%1], 16;\n"
                 :: "r"(smem_addr), "l"(gptr));
}
__device__ __forceinline__ unsigned ld_acq_u32(const unsigned* p) {
    unsigned v;
    asm volatile("ld.global.acquire.gpu.b32 %0, [%1];" : "=r"(v) : "l"(p));
    return v;
}
__device__ __forceinline__ void red_rel_add(unsigned* p, unsigned v) {
    asm volatile("red.global.release.gpu.add.u32 [%0], %1;" :: "l"(p), "r"(v) : "memory");
}

// ---------------- init ----------------
__global__ void k_init(const float* __restrict__ h0, const float* __restrict__ c0,
                       const int* __restrict__ tags) {
    int j = threadIdx.x;            // 512 threads
    g_h[0][j] = h0[j];
    g_c[j]    = c0[j];
    if (j < NTAG) g_tag_cnt[j] = 0;
    if (j == 0)   g_ctr = 0;
    __syncthreads();
    int tag = tags[j];
    int pos = atomicAdd(&g_tag_cnt[tag], 1);
    g_tag_list[tag * SEQ + pos] = j;
}

// ---------------- embedding gather ----------------
__global__ void k_embed(const int* __restrict__ x, const float* __restrict__ emb) {
    int t = blockIdx.x;             // grid 512, block 128
    int row = x[t];
    const float4* src = (const float4*)emb + (size_t)row * (EMB / 4);
    float4* dst = (float4*)g_embeds + (size_t)t * (EMB / 4);
    dst[threadIdx.x] = src[threadIdx.x];
}

// ---------------- precompute P[t] = Wih[tag_t] @ x_t + bih + bhh ----------------
// 2 rows per thread: halves Xs LDS traffic per FLOP (kernel is L1-bound at 57.7%).
// grid: (36 tags, 8 row-blocks of 256, 32 chunks of 16 timesteps). block 128.
__global__ void k_precompute(const float* __restrict__ Wih,
                             const float* __restrict__ bih,
                             const float* __restrict__ bhh) {
    __shared__ float4 Xs[16 * 128];
    __shared__ int ts[16];
    int g   = blockIdx.x;
    int cnt = g_tag_cnt[g];
    int c0  = blockIdx.z * 16;
    if (c0 >= cnt) return;
    int m   = min(16, cnt - c0);
    int tid = threadIdx.x;

    if (tid < 16) ts[tid] = (tid < m) ? g_tag_list[g * SEQ + c0 + tid] : 0;
    __syncthreads();

    #pragma unroll
    for (int it = 0; it < 16; ++it) {
        int i = it * 128 + tid;
        int n = i >> 7, kk = i & 127;
        Xs[i] = (n < m) ? ((const float4*)g_embeds)[(size_t)ts[n] * 128 + kk]
                        : make_float4(0.f, 0.f, 0.f, 0.f);
    }
    __syncthreads();

    int r = blockIdx.y * 256 + tid;   // rows r and r+128
    const float4* w0p = (const float4*)(Wih + ((size_t)g * G4 + r) * EMB);
    const float4* w1p = w0p + 128 * (EMB / 4);

    float acc0[16], acc1[16];
    #pragma unroll
    for (int n = 0; n < 16; ++n) { acc0[n] = 0.f; acc1[n] = 0.f; }

    for (int kk = 0; kk < 128; ++kk) {
        float4 wa = __ldg(w0p + kk);
        float4 wb = __ldg(w1p + kk);
        #pragma unroll
        for (int n = 0; n < 16; ++n) {
            float4 xv = Xs[n * 128 + kk];   // one LDS feeds two rows
            acc0[n] += wa.x * xv.x + wa.y * xv.y + wa.z * xv.z + wa.w * xv.w;
            acc1[n] += wb.x * xv.x + wb.y * xv.y + wb.z * xv.z + wb.w * xv.w;
        }
    }

    float bias0 = bih[g * G4 + r]       + bhh[g * G4 + r];
    float bias1 = bih[g * G4 + r + 128] + bhh[g * G4 + r + 128];
    for (int n = 0; n < m; ++n) {
        g_P[(size_t)ts[n] * G4 + r]       = acc0[n] + bias0;
        g_P[(size_t)ts[n] * G4 + r + 128] = acc1[n] + bias1;
    }
}

// ---------------- persistent recurrent kernel (R11 base + parallel gates) ---------
// 128 CTAs x 288 threads (9 warps). CTA b owns j in [4b,4b+4).
// warp 0: sync/h/gates (16 lanes: one gate nonlinearity each).
// warps 1-8 (idx=w-1): rows {p*512+j,(p+1)*512+j}. cp.async double-buffered ring.
__global__ void __launch_bounds__(288, 1) k_seq(const float* __restrict__ Whh,
                                                const int* __restrict__ tags_g) {
    extern __shared__ char dsm[];
    float*  wsb   = (float*)dsm;                         // [2][8 warps][1024]  64 KB
    float4* hs4   = (float4*)(dsm + 65536);              // h stage, 512 floats
    int*    stags = (int*)  (dsm + 65536 + 2048);        // 512 ints
    float*  sred  = (float*)(dsm + 65536 + 4096);        // 16 floats

    int tid  = threadIdx.x;
    int lane = tid & 31;
    int w    = tid >> 5;                 // 0..8
    int b    = blockIdx.x;
    int idx  = w - 1;                    // compute-warp index 0..7 (w>=1)
    int j    = b * 4 + (idx & 3);
    int r0   = ((idx >> 2) * 2) * HID + j;

    for (int i = tid; i < SEQ; i += 288) stags[i] = tags_g[i];
    __syncthreads();

    // warp0: lane lm=lane&15 handles gate gg=(lm>>2) of local column jl=(lm&3)
    int lm = lane & 15;
    int jl = lm & 3;
    int gg = lm >> 2;
    int sidx = (gg < 2) ? (2 * jl + gg) : (8 + 2 * jl + (gg - 2));

    float c = (w == 0) ? ((lane < 4) ? g_c[b * 4 + lane] : 0.f) : 0.f;

    uint32_t wbase = 0;
    const size_t ROWSTRIDE = (size_t)HID;
    if (w > 0) {
        wbase = (uint32_t)__cvta_generic_to_shared(wsb + idx * 1024);
        #pragma unroll
        for (int s = 0; s < 2; ++s) {
            const float* s0 = Whh + ((size_t)stags[s] * G4 + r0) * ROWSTRIDE;
            const float* s1 = s0 + 512 * ROWSTRIDE;
            uint32_t d = wbase + s * 32768;
            #pragma unroll
            for (int k = 0; k < 4; ++k) {
                cp16(d +        (lane + 32 * k) * 16, s0 + (lane + 32 * k) * 4);
                cp16(d + 2048 + (lane + 32 * k) * 16, s1 + (lane + 32 * k) * 4);
            }
            asm volatile("cp.async.commit_group;\n" ::: "memory");
        }
    }

    for (int t = 0; t < SEQ; ++t) {
        int slot = t & 1;

        if (w == 0) {
            // P prefetch: one element per lane (gate gg, column b*4+jl)
            float pv = __ldg(g_P + (size_t)t * G4 + gg * 512 + b * 4 + jl);
            // poll with backoff, then fetch h -> smem
            unsigned target = (unsigned)NCTA * (unsigned)t;
            if (ld_acq_u32(&g_ctr) < target) {
                do { __nanosleep(128); } while (ld_acq_u32(&g_ctr) < target);
            }
            const float4* hg = (const float4*)g_h[t & 1];
            hs4[lane]      = __ldcg(hg + lane);
            hs4[lane + 32] = __ldcg(hg + lane + 32);
            hs4[lane + 64] = __ldcg(hg + lane + 64);
            hs4[lane + 96] = __ldcg(hg + lane + 96);
            __syncthreads();   // bar1: h staged
            __syncthreads();   // bar2: sred ready

            // parallel nonlinearities: 16 lanes, one exp each (gate 2 -> tanh)
            float val = sred[sidx] + pv;
            float arg = (gg == 2) ? (2.0f * val) : val;
            float r1  = 1.0f / (1.0f + __expf(-arg));
            float nl  = (gg == 2) ? (2.0f * r1 - 1.0f) : r1;

            float iv = nl;                                    // valid lanes 0-3
            float fv = __shfl_sync(0xffffffffu, nl, lane + 4);
            float gv = __shfl_sync(0xffffffffu, nl, lane + 8);
            float ov = __shfl_sync(0xffffffffu, nl, lane + 12);

            c = fv * c + iv * gv;                             // live in lanes 0-3
            float e2 = __expf(-2.0f * c);
            float hv = ov * (2.0f / (1.0f + e2) - 1.0f);

            float h1v = __shfl_sync(0xffffffffu, hv, 1);
            float h2v = __shfl_sync(0xffffffffu, hv, 2);
            float h3v = __shfl_sync(0xffffffffu, hv, 3);
            if (lane == 0) {
                float4 hq = make_float4(hv, h1v, h2v, h3v);
                *(float4*)&g_h[(t + 1) & 1][b * 4] = hq;   // one 16B store
                red_rel_add(&g_ctr, 1u);                   // release orders it
            }
        } else {
            // compute warps: weight LDS + refill overlap warp 0's poll
            asm volatile("cp.async.wait_group 1;\n" ::: "memory");
            const float4* wr = (const float4*)(wsb + slot * 8192 + idx * 1024);
            float4 b0 = wr[lane],            b1 = wr[lane + 32];
            float4 b2 = wr[lane + 64],       b3 = wr[lane + 96];
            float4 e0 = wr[128 + lane],      e1 = wr[128 + lane + 32];
            float4 e2 = wr[128 + lane + 64], e3 = wr[128 + lane + 96];

            if (t + 2 < SEQ) {
                const float* s0 = Whh + ((size_t)stags[t + 2] * G4 + r0) * ROWSTRIDE;
                const float* s1 = s0 + 512 * ROWSTRIDE;
                uint32_t d = wbase + slot * 32768;
                #pragma unroll
                for (int k = 0; k < 4; ++k) {
                    cp16(d +        (lane + 32 * k) * 16, s0 + (lane + 32 * k) * 4);
                    cp16(d + 2048 + (lane + 32 * k) * 16, s1 + (lane + 32 * k) * 4);
                }
            }
            asm volatile("cp.async.commit_group;\n" ::: "memory");

            __syncthreads();   // bar1: wait for h in smem

            float4 h0 = hs4[lane];
            float4 h1 = hs4[lane + 32];
            float4 h2 = hs4[lane + 64];
            float4 h3 = hs4[lane + 96];
            float acc0 = b0.x*h0.x + b0.y*h0.y + b0.z*h0.z + b0.w*h0.w
                       + b1.x*h1.x + b1.y*h1.y + b1.z*h1.z + b1.w*h1.w
                       + b2.x*h2.x + b2.y*h2.y + b2.z*h2.z + b2.w*h2.w
                       + b3.x*h3.x + b3.y*h3.y + b3.z*h3.z + b3.w*h3.w;
            float acc1 = e0.x*h0.x + e0.y*h0.y + e0.z*h0.z + e0.w*h0.w
                       + e1.x*h1.x + e1.y*h1.y + e1.z*h1.z + e1.w*h1.w
                       + e2.x*h2.x + e2.y*h2.y + e2.z*h2.z + e2.w*h2.w
                       + e3.x*h3.x + e3.y*h3.y + e3.z*h3.z + e3.w*h3.w;
            #pragma unroll
            for (int off = 16; off; off >>= 1) {
                acc0 += __shfl_down_sync(0xffffffffu, acc0, off);
                acc1 += __shfl_down_sync(0xffffffffu, acc1, off);
            }
            if (lane == 0) { sred[idx * 2] = acc0; sred[idx * 2 + 1] = acc1; }
            __syncthreads();   // bar2: sred published
        }
    }

    if (w == 0 && lane < 4) g_c[b * 4 + lane] = c;
}

// ---------------- final fc + sigmoid + pack outputs ----------------
__global__ void k_final(const float* __restrict__ Wfc, const float* __restrict__ bfc,
                        float* __restrict__ out, int out_size) {
    __shared__ float red[16];
    int tid = threadIdx.x;            // 512 threads
    float hv = g_h[0][tid];           // after step 511, h lives in buffer 0
    float v = hv * Wfc[tid];
    #pragma unroll
    for (int off = 16; off; off >>= 1) v += __shfl_down_sync(0xffffffffu, v, off);
    if ((tid & 31) == 0) red[tid >> 5] = v;
    __syncthreads();
    if (tid < 16) {
        float s = red[tid];
        #pragma unroll
        for (int off = 8; off; off >>= 1) s += __shfl_down_sync(0x0000ffffu, s, off);
        if (tid == 0 && out_size > 0)
            out[0] = sigmoidf_(s + bfc[0]);
    }
    if (1 + tid < out_size)   out[1 + tid]   = hv;
    if (513 + tid < out_size) out[513 + tid] = g_c[tid];
}

// ---------------- launcher ----------------
extern "C" void kernel_launch(void* const* d_in, const int* in_sizes, int n_in,
                              void* d_out, int out_size) {
    const int*   x    = (const int*)d_in[0];
    const int*   tags = (const int*)d_in[1];
    const float* h0   = (const float*)d_in[2];
    const float* c0   = (const float*)d_in[3];
    const float* emb  = (const float*)d_in[4];
    const float* Wih  = (const float*)d_in[5];
    const float* Whh  = (const float*)d_in[6];
    const float* bih  = (const float*)d_in[7];
    const float* bhh  = (const float*)d_in[8];
    const float* Wfc  = (const float*)d_in[9];
    const float* bfc  = (const float*)d_in[10];
    (void)in_sizes; (void)n_in;

    const int SMEM_SEQ = 65536 + 2048 + 2048 + 128;   // 68.3 KB dynamic
    cudaFuncSetAttribute(k_seq, cudaFuncAttributeMaxDynamicSharedMemorySize, SMEM_SEQ);

    k_init<<<1, 512>>>(h0, c0, tags);
    k_embed<<<512, 128>>>(x, emb);
    k_precompute<<<dim3(NTAG, 8, 32), 128>>>(Wih, bih, bhh);
    k_seq<<<NCTA, 288, SMEM_SEQ>>>(Whh, tags);
    k_final<<<1, 512>>>(Wfc, bfc, (float*)d_out, out_size);
}

// round 14
// speedup vs baseline: 1.3252x; 1.2304x over previous
#include <cuda_runtime.h>
#include <math.h>
#include <stdint.h>

#define NTAG 36
#define SEQ  512
#define HID  512
#define EMB  512
#define G4   2048   // 4*HID
#define NCTA 128

// ---------------- device scratch (no allocations allowed) ----------------
__device__ __align__(16) float g_embeds[SEQ * EMB];        // 1 MB
__device__ __align__(16) float g_P[SEQ * G4];              // 4 MB: Wih@x + bih + bhh
// tagged h publication: word = (step_tag << 32) | float_bits(h). One 128B slot per
// CTA (words 0..3 used) so polls spread over 128 L2 lines instead of 32.
__device__ __align__(128) unsigned long long g_pub[2][NCTA][16];
__device__ __align__(16) float g_c[HID];
__device__ int g_tag_list[NTAG * SEQ];
__device__ int g_tag_cnt[NTAG];

__device__ __forceinline__ float sigmoidf_(float x) {
    return 1.0f / (1.0f + __expf(-x));
}
__device__ __forceinline__ float tanhf_(float x) {
    return 2.0f / (1.0f + __expf(-2.0f * x)) - 1.0f;
}
__device__ __forceinline__ void cp16(uint32_t smem_addr, const void* gptr) {
    asm volatile("cp.async.cg.shared.global [%0], [%1], 16;\n"
                 :: "r"(smem_addr), "l"(gptr));
}
__device__ __forceinline__ void ldcg_u64x2(const unsigned long long* p,
                                           unsigned long long& a, unsigned long long& b) {
    asm volatile("ld.global.cg.v2.u64 {%0,%1}, [%2];" : "=l"(a), "=l"(b) : "l"(p));
}
__device__ __forceinline__ void stcg_u64(unsigned long long* p, unsigned long long v) {
    asm volatile("st.global.cg.b64 [%0], %1;" :: "l"(p), "l"(v) : "memory");
}

// ---------------- init ----------------
__global__ void k_init(const float* __restrict__ h0, const float* __restrict__ c0,
                       const int* __restrict__ tags) {
    int j = threadIdx.x;            // 512 threads
    // buffer 0: h0 with tag 0; buffer 1: sentinel (never matches 0..512)
    g_pub[0][j >> 2][j & 3] = (unsigned)__float_as_uint(h0[j]);   // tag 0 in high bits
    g_pub[1][j >> 2][j & 3] = 0xFFFFFFFF00000000ull;
    g_c[j] = c0[j];
    if (j < NTAG) g_tag_cnt[j] = 0;
    __syncthreads();
    int tag = tags[j];
    int pos = atomicAdd(&g_tag_cnt[tag], 1);
    g_tag_list[tag * SEQ + pos] = j;
}

// ---------------- embedding gather ----------------
__global__ void k_embed(const int* __restrict__ x, const float* __restrict__ emb) {
    int t = blockIdx.x;             // grid 512, block 128
    int row = x[t];
    const float4* src = (const float4*)emb + (size_t)row * (EMB / 4);
    float4* dst = (float4*)g_embeds + (size_t)t * (EMB / 4);
    dst[threadIdx.x] = src[threadIdx.x];
}

// ---------------- precompute P[t] = Wih[tag_t] @ x_t + bih + bhh (148us config) ----
__global__ void k_precompute(const float* __restrict__ Wih,
                             const float* __restrict__ bih,
                             const float* __restrict__ bhh) {
    __shared__ float4 Xs[16 * 128];
    __shared__ int ts[16];
    int g   = blockIdx.x;
    int cnt = g_tag_cnt[g];
    int c0  = blockIdx.z * 16;
    if (c0 >= cnt) return;
    int m   = min(16, cnt - c0);
    int tid = threadIdx.x;

    if (tid < 16) ts[tid] = (tid < m) ? g_tag_list[g * SEQ + c0 + tid] : 0;
    __syncthreads();

    #pragma unroll
    for (int it = 0; it < 16; ++it) {
        int i = it * 128 + tid;
        int n = i >> 7, kk = i & 127;
        Xs[i] = (n < m) ? ((const float4*)g_embeds)[(size_t)ts[n] * 128 + kk]
                        : make_float4(0.f, 0.f, 0.f, 0.f);
    }
    __syncthreads();

    int r = blockIdx.y * 128 + tid;
    const float4* wrow = (const float4*)(Wih + ((size_t)g * G4 + r) * EMB);

    float acc[16];
    #pragma unroll
    for (int n = 0; n < 16; ++n) acc[n] = 0.f;

    #pragma unroll 2
    for (int kk = 0; kk < 128; ++kk) {
        float4 w = __ldg(wrow + kk);
        #pragma unroll
        for (int n = 0; n < 16; ++n) {
            float4 xv = Xs[n * 128 + kk];
            acc[n] += w.x * xv.x + w.y * xv.y + w.z * xv.z + w.w * xv.w;
        }
    }

    float bias = bih[g * G4 + r] + bhh[g * G4 + r];
    for (int n = 0; n < m; ++n)
        g_P[(size_t)ts[n] * G4 + r] = acc[n] + bias;
}

// ---------------- persistent recurrent kernel (R11 base + tagged-h sync) ----------
// 128 CTAs x 288 threads (9 warps). CTA b owns j in [4b,4b+4).
// warp 0: poll/h/gates. warps 1-8 (idx=w-1): rows {p*512+j,(p+1)*512+j}.
// Sync: h published as (tag|h) in 8B atoms, one 128B slot per CTA. Consumer's
// poll IS the fetch (no counter, no release, no second round-trip). Backoff-
// throttled, line-spread polling (fixes R9's poll storm).
__global__ void __launch_bounds__(288, 1) k_seq(const float* __restrict__ Whh,
                                                const int* __restrict__ tags_g) {
    extern __shared__ char dsm[];
    float*  wsb   = (float*)dsm;                         // [2][8 warps][1024]  64 KB
    float*  hs    = (float*)(dsm + 65536);               // h stage, 512 floats
    int*    stags = (int*)  (dsm + 65536 + 2048);        // 512 ints
    float*  sred  = (float*)(dsm + 65536 + 4096);        // 16 floats

    int tid  = threadIdx.x;
    int lane = tid & 31;
    int w    = tid >> 5;                 // 0..8
    int b    = blockIdx.x;
    int idx  = w - 1;                    // compute-warp index 0..7 (w>=1)
    int j    = b * 4 + (idx & 3);
    int r0   = ((idx >> 2) * 2) * HID + j;

    for (int i = tid; i < SEQ; i += 288) stags[i] = tags_g[i];
    __syncthreads();

    float c = (tid < 4) ? g_c[b * 4 + tid] : 0.f;

    uint32_t wbase = 0;
    const size_t ROWSTRIDE = (size_t)HID;
    if (w > 0) {
        wbase = (uint32_t)__cvta_generic_to_shared(wsb + idx * 1024);
        #pragma unroll
        for (int s = 0; s < 2; ++s) {
            const float* s0 = Whh + ((size_t)stags[s] * G4 + r0) * ROWSTRIDE;
            const float* s1 = s0 + 512 * ROWSTRIDE;
            uint32_t d = wbase + s * 32768;
            #pragma unroll
            for (int k = 0; k < 4; ++k) {
                cp16(d +        (lane + 32 * k) * 16, s0 + (lane + 32 * k) * 4);
                cp16(d + 2048 + (lane + 32 * k) * 16, s1 + (lane + 32 * k) * 4);
            }
            asm volatile("cp.async.commit_group;\n" ::: "memory");
        }
    }

    for (int t = 0; t < SEQ; ++t) {
        int slot = t & 1;

        if (w == 0) {
            // P prefetch (lanes 0-3)
            float pi = 0.f, pf = 0.f, pg = 0.f, po = 0.f;
            if (lane < 4) {
                const float* Pt = g_P + (size_t)t * G4 + b * 4 + lane;
                pi = __ldg(Pt);
                pf = __ldg(Pt + 512);
                pg = __ldg(Pt + 1024);
                po = __ldg(Pt + 1536);
            }

            // poll tagged h: detect == fetch. lane L owns CTA slots L,L+32,L+64,L+96.
            const unsigned long long* pb = &g_pub[t & 1][0][0];
            unsigned long long a0[4], a1[4], a2[4], a3[4];
            for (;;) {
                bool ok = true;
                #pragma unroll
                for (int q = 0; q < 4; ++q) {
                    const unsigned long long* sp = pb + (size_t)(lane + 32 * q) * 16;
                    ldcg_u64x2(sp,     a0[q], a1[q]);
                    ldcg_u64x2(sp + 2, a2[q], a3[q]);
                    ok &= ((unsigned)(a0[q] >> 32) == (unsigned)t)
                        & ((unsigned)(a1[q] >> 32) == (unsigned)t)
                        & ((unsigned)(a2[q] >> 32) == (unsigned)t)
                        & ((unsigned)(a3[q] >> 32) == (unsigned)t);
                }
                if (__all_sync(0xffffffffu, ok)) break;
                __nanosleep(100);      // throttle: keep pub lines unsaturated
            }
            // stage h: slot s carries h[4s..4s+3]
            #pragma unroll
            for (int q = 0; q < 4; ++q) {
                int s = lane + 32 * q;
                ((float4*)hs)[s] = make_float4(
                    __uint_as_float((unsigned)a0[q]),
                    __uint_as_float((unsigned)a1[q]),
                    __uint_as_float((unsigned)a2[q]),
                    __uint_as_float((unsigned)a3[q]));
            }
            __syncthreads();   // bar1: h staged
            __syncthreads();   // bar2: sred ready

            if (lane < 4) {
                float gi = sred[2 * lane]     + pi;
                float gf = sred[2 * lane + 1] + pf;
                float gg = sred[8 + 2 * lane] + pg;
                float go = sred[9 + 2 * lane] + po;
                float iv = sigmoidf_(gi);
                float fv = sigmoidf_(gf);
                float gv = tanhf_(gg);
                float ov = sigmoidf_(go);
                c = fv * c + iv * gv;
                float hv = ov * tanhf_(c);
                // publish: tag travels with h in one 8B atom; 4 lanes = one 32B sector
                unsigned long long pk =
                    ((unsigned long long)(unsigned)(t + 1) << 32) |
                    (unsigned)__float_as_uint(hv);
                stcg_u64(&g_pub[(t + 1) & 1][b][lane], pk);
            }
        } else {
            // compute warps: weight LDS + refill overlap warp 0's poll
            asm volatile("cp.async.wait_group 1;\n" ::: "memory");
            const float4* wr = (const float4*)(wsb + slot * 8192 + idx * 1024);
            float4 b0 = wr[lane],            b1 = wr[lane + 32];
            float4 b2 = wr[lane + 64],       b3 = wr[lane + 96];
            float4 e0 = wr[128 + lane],      e1 = wr[128 + lane + 32];
            float4 e2 = wr[128 + lane + 64], e3 = wr[128 + lane + 96];

            if (t + 2 < SEQ) {
                const float* s0 = Whh + ((size_t)stags[t + 2] * G4 + r0) * ROWSTRIDE;
                const float* s1 = s0 + 512 * ROWSTRIDE;
                uint32_t d = wbase + slot * 32768;
                #pragma unroll
                for (int k = 0; k < 4; ++k) {
                    cp16(d +        (lane + 32 * k) * 16, s0 + (lane + 32 * k) * 4);
                    cp16(d + 2048 + (lane + 32 * k) * 16, s1 + (lane + 32 * k) * 4);
                }
            }
            asm volatile("cp.async.commit_group;\n" ::: "memory");

            __syncthreads();   // bar1: wait for h in smem

            const float4* hv4 = (const float4*)hs;
            float4 h0 = hv4[lane];
            float4 h1 = hv4[lane + 32];
            float4 h2 = hv4[lane + 64];
            float4 h3 = hv4[lane + 96];
            float acc0 = b0.x*h0.x + b0.y*h0.y + b0.z*h0.z + b0.w*h0.w
                       + b1.x*h1.x + b1.y*h1.y + b1.z*h1.z + b1.w*h1.w
                       + b2.x*h2.x + b2.y*h2.y + b2.z*h2.z + b2.w*h2.w
                       + b3.x*h3.x + b3.y*h3.y + b3.z*h3.z + b3.w*h3.w;
            float acc1 = e0.x*h0.x + e0.y*h0.y + e0.z*h0.z + e0.w*h0.w
                       + e1.x*h1.x + e1.y*h1.y + e1.z*h1.z + e1.w*h1.w
                       + e2.x*h2.x + e2.y*h2.y + e2.z*h2.z + e2.w*h2.w
                       + e3.x*h3.x + e3.y*h3.y + e3.z*h3.z + e3.w*h3.w;
            #pragma unroll
            for (int off = 16; off; off >>= 1) {
                acc0 += __shfl_down_sync(0xffffffffu, acc0, off);
                acc1 += __shfl_down_sync(0xffffffffu, acc1, off);
            }
            if (lane == 0) { sred[idx * 2] = acc0; sred[idx * 2 + 1] = acc1; }
            __syncthreads();   // bar2: sred published
        }
    }

    if (tid < 4) g_c[b * 4 + tid] = c;
}

// ---------------- final fc + sigmoid + pack outputs ----------------
__global__ void k_final(const float* __restrict__ Wfc, const float* __restrict__ bfc,
                        float* __restrict__ out, int out_size) {
    __shared__ float red[16];
    int tid = threadIdx.x;            // 512 threads
    // step 511 published tag 512 into buffer (512&1)=0
    float hv = __uint_as_float((unsigned)g_pub[0][tid >> 2][tid & 3]);
    float v = hv * Wfc[tid];
    #pragma unroll
    for (int off = 16; off; off >>= 1) v += __shfl_down_sync(0xffffffffu, v, off);
    if ((tid & 31) == 0) red[tid >> 5] = v;
    __syncthreads();
    if (tid < 16) {
        float s = red[tid];
        #pragma unroll
        for (int off = 8; off; off >>= 1) s += __shfl_down_sync(0x0000ffffu, s, off);
        if (tid == 0 && out_size > 0)
            out[0] = sigmoidf_(s + bfc[0]);
    }
    if (1 + tid < out_size)   out[1 + tid]   = hv;
    if (513 + tid < out_size) out[513 + tid] = g_c[tid];
}

// ---------------- launcher ----------------
extern "C" void kernel_launch(void* const* d_in, const int* in_sizes, int n_in,
                              void* d_out, int out_size) {
    const int*   x    = (const int*)d_in[0];
    const int*   tags = (const int*)d_in[1];
    const float* h0   = (const float*)d_in[2];
    const float* c0   = (const float*)d_in[3];
    const float* emb  = (const float*)d_in[4];
    const float* Wih  = (const float*)d_in[5];
    const float* Whh  = (const float*)d_in[6];
    const float* bih  = (const float*)d_in[7];
    const float* bhh  = (const float*)d_in[8];
    const float* Wfc  = (const float*)d_in[9];
    const float* bfc  = (const float*)d_in[10];
    (void)in_sizes; (void)n_in;

    const int SMEM_SEQ = 65536 + 2048 + 2048 + 128;   // 68.3 KB dynamic
    cudaFuncSetAttribute(k_seq, cudaFuncAttributeMaxDynamicSharedMemorySize, SMEM_SEQ);

    k_init<<<1, 512>>>(h0, c0, tags);
    k_embed<<<512, 128>>>(x, emb);
    k_precompute<<<dim3(NTAG, 16, 32), 128>>>(Wih, bih, bhh);
    k_seq<<<NCTA, 288, SMEM_SEQ>>>(Whh, tags);
    k_final<<<1, 512>>>(Wfc, bfc, (float*)d_out, out_size);
}